// round 1
// baseline (speedup 1.0000x reference)
#include <cuda_runtime.h>
#include <cstdint>

// Sparse Adam: N=1e6 rows, M=250k visible, D=32, out = [3, N, D] f32.
// Inputs (metadata order): param[N*D] f32, grad[M*D] f32, exp_avg[N*D] f32,
// exp_avg_sq[N*D] f32, index[M] i32, step scalar i32.

#define B1 0.9f
#define B2 0.999f
#define EPS 1e-15f
#define LR  1.6e-4f

// Kernel 1: bulk copy of the three state arrays into the three output slabs.
// Each thread moves one float4 from each of the three sources (48B R + 48B W).
__global__ void copy3_kernel(const float4* __restrict__ p,
                             const float4* __restrict__ ea,
                             const float4* __restrict__ eas,
                             float4* __restrict__ out,
                             long n4) {
    long i = (long)blockIdx.x * blockDim.x + threadIdx.x;
    if (i >= n4) return;
    out[i]          = p[i];
    out[n4 + i]     = ea[i];
    out[2 * n4 + i] = eas[i];
}

// Kernel 2: Adam update for the M visible rows. Thread t handles float4 chunk
// c = t&7 of visible row r = t>>3. Gathers original state at index[r],
// computes update, scatters all three results into the output slabs.
__global__ void adam_update_kernel(const float* __restrict__ param,
                                   const float* __restrict__ grad,
                                   const float* __restrict__ exp_avg,
                                   const float* __restrict__ exp_avg_sq,
                                   const int*   __restrict__ index,
                                   const int*   __restrict__ step_ptr,
                                   float* __restrict__ out,
                                   int M, long ND) {
    int gid = blockIdx.x * blockDim.x + threadIdx.x;
    int total = M * 8;             // 8 float4 chunks per row of 32
    if (gid >= total) return;
    int r = gid >> 3;
    int c = gid & 7;

    int step = step_ptr ? step_ptr[0] : 1000;
    // bias corrections: B1^1000 underflows f32 -> bc1 = 1.0 (matches the
    // double-precision python reference to full f32 precision);
    // bc2 error ~1e-5 rel, well under the 1e-3 threshold.
    float bc1 = 1.0f - __powf(B1, (float)step);
    float bc2 = 1.0f - __powf(B2, (float)step);
    float inv_sqrt_bc2 = rsqrtf(bc2);
    float lr_c = LR / bc1;

    int idx = index[r];
    long go = (long)r * 32 + (long)c * 4;   // grad offset (dense by M-row)
    long po = (long)idx * 32 + (long)c * 4; // state offset (gather by index)

    float4 g = *reinterpret_cast<const float4*>(grad + go);
    float4 p = *reinterpret_cast<const float4*>(param + po);
    float4 a = *reinterpret_cast<const float4*>(exp_avg + po);
    float4 s = *reinterpret_cast<const float4*>(exp_avg_sq + po);

    // ea  = ea*B1 + (1-B1)*g
    a.x = a.x * B1 + (1.0f - B1) * g.x;
    a.y = a.y * B1 + (1.0f - B1) * g.y;
    a.z = a.z * B1 + (1.0f - B1) * g.z;
    a.w = a.w * B1 + (1.0f - B1) * g.w;
    // eas = eas*B2 + (1-B2)*g*g
    s.x = s.x * B2 + (1.0f - B2) * g.x * g.x;
    s.y = s.y * B2 + (1.0f - B2) * g.y * g.y;
    s.z = s.z * B2 + (1.0f - B2) * g.z * g.z;
    s.w = s.w * B2 + (1.0f - B2) * g.w * g.w;
    // denom = sqrt(eas)/sqrt(bc2) + eps ; p -= (lr/bc1) * ea / denom
    p.x -= lr_c * a.x / (sqrtf(s.x) * inv_sqrt_bc2 + EPS);
    p.y -= lr_c * a.y / (sqrtf(s.y) * inv_sqrt_bc2 + EPS);
    p.z -= lr_c * a.z / (sqrtf(s.z) * inv_sqrt_bc2 + EPS);
    p.w -= lr_c * a.w / (sqrtf(s.w) * inv_sqrt_bc2 + EPS);

    *reinterpret_cast<float4*>(out + po)          = p;
    *reinterpret_cast<float4*>(out + ND + po)     = a;
    *reinterpret_cast<float4*>(out + 2 * ND + po) = s;
}

extern "C" void kernel_launch(void* const* d_in, const int* in_sizes, int n_in,
                              void* d_out, int out_size) {
    const float* param      = (const float*)d_in[0];
    const float* grad       = (const float*)d_in[1];
    const float* exp_avg    = (const float*)d_in[2];
    const float* exp_avg_sq = (const float*)d_in[3];
    const int*   index      = (const int*)d_in[4];
    const int*   step_ptr   = (n_in > 5) ? (const int*)d_in[5] : nullptr;

    long ND = (long)in_sizes[0];        // N*D elements of param
    int  M  = in_sizes[4];              // number of visible indices
    long n4 = ND / 4;

    float* out = (float*)d_out;

    // Pass 1: copy state -> output slabs (768 MB streaming)
    {
        int threads = 256;
        long blocks = (n4 + threads - 1) / threads;
        copy3_kernel<<<(unsigned)blocks, threads>>>(
            (const float4*)param, (const float4*)exp_avg,
            (const float4*)exp_avg_sq, (float4*)out, n4);
    }

    // Pass 2: Adam update + scatter for the M visible rows
    {
        int threads = 256;
        int total = M * 8;
        int blocks = (total + threads - 1) / threads;
        adam_update_kernel<<<blocks, threads>>>(
            param, grad, exp_avg, exp_avg_sq, index, step_ptr,
            out, M, ND);
    }
}

// round 2
// speedup vs baseline: 1.1893x; 1.1893x over previous
#include <cuda_runtime.h>
#include <cstdint>

// Sparse Adam: N=1e6 rows, M=250k visible, D=32, out = [3, N, D] f32.
// Inputs (metadata order): param[N*D] f32, grad[M*D] f32, exp_avg[N*D] f32,
// exp_avg_sq[N*D] f32, index[M] i32, step scalar i32.

#define B1 0.9f
#define B2 0.999f
#define EPS 1e-15f
#define LR  1.6e-4f

#define N_MAX 1048576  // >= N = 1,000,000 rows

// Scratch: inverse index map (row -> visible slot, or -1). 4 MB.
__device__ int g_inv[N_MAX];

__global__ void init_inv_kernel(int n) {
    int i = blockIdx.x * blockDim.x + threadIdx.x;
    if (i < n) g_inv[i] = -1;
}

__global__ void scatter_inv_kernel(const int* __restrict__ index, int M) {
    int r = blockIdx.x * blockDim.x + threadIdx.x;
    if (r < M) g_inv[index[r]] = r;
}

// Fused pass: one thread per float4 chunk of the N*D state.
// Reads param/exp_avg/exp_avg_sq, applies Adam where the row is visible,
// writes all three output slabs.
__global__ __launch_bounds__(256) void fused_adam_kernel(
        const float4* __restrict__ param,
        const float*  __restrict__ grad,
        const float4* __restrict__ exp_avg,
        const float4* __restrict__ exp_avg_sq,
        const int*    __restrict__ step_ptr,
        float4* __restrict__ out,
        long n4) {
    long gid = (long)blockIdx.x * blockDim.x + threadIdx.x;
    if (gid >= n4) return;

    int row = (int)(gid >> 3);   // 8 float4 chunks per 32-float row
    int c   = (int)(gid & 7);

    float4 p = param[gid];
    float4 a = exp_avg[gid];
    float4 s = exp_avg_sq[gid];

    int r = g_inv[row];
    if (r >= 0) {
        int step = step_ptr ? step_ptr[0] : 1000;
        // bc1: 0.9^1000 underflows f32 -> bc1 = 1.0 exactly (matches the
        // float64-exponent reference); bc2 rel-err ~1e-5 << 1e-3 threshold.
        float bc1 = 1.0f - __powf(B1, (float)step);
        float bc2 = 1.0f - __powf(B2, (float)step);
        float inv_sqrt_bc2 = rsqrtf(bc2);
        float lr_c = LR / bc1;

        float4 g = *reinterpret_cast<const float4*>(grad + (long)r * 32 + c * 4);

        a.x = a.x * B1 + (1.0f - B1) * g.x;
        a.y = a.y * B1 + (1.0f - B1) * g.y;
        a.z = a.z * B1 + (1.0f - B1) * g.z;
        a.w = a.w * B1 + (1.0f - B1) * g.w;

        s.x = s.x * B2 + (1.0f - B2) * g.x * g.x;
        s.y = s.y * B2 + (1.0f - B2) * g.y * g.y;
        s.z = s.z * B2 + (1.0f - B2) * g.z * g.z;
        s.w = s.w * B2 + (1.0f - B2) * g.w * g.w;

        p.x -= lr_c * a.x / (sqrtf(s.x) * inv_sqrt_bc2 + EPS);
        p.y -= lr_c * a.y / (sqrtf(s.y) * inv_sqrt_bc2 + EPS);
        p.z -= lr_c * a.z / (sqrtf(s.z) * inv_sqrt_bc2 + EPS);
        p.w -= lr_c * a.w / (sqrtf(s.w) * inv_sqrt_bc2 + EPS);
    }

    out[gid]          = p;
    out[n4 + gid]     = a;
    out[2 * n4 + gid] = s;
}

extern "C" void kernel_launch(void* const* d_in, const int* in_sizes, int n_in,
                              void* d_out, int out_size) {
    const float* param      = (const float*)d_in[0];
    const float* grad       = (const float*)d_in[1];
    const float* exp_avg    = (const float*)d_in[2];
    const float* exp_avg_sq = (const float*)d_in[3];
    const int*   index      = (const int*)d_in[4];
    const int*   step_ptr   = (n_in > 5) ? (const int*)d_in[5] : nullptr;

    long ND = (long)in_sizes[0];   // N*D
    int  N  = (int)(ND / 32);
    int  M  = in_sizes[4];
    long n4 = ND / 4;

    float* out = (float*)d_out;

    {   // inv[i] = -1
        int threads = 256;
        int blocks = (N + threads - 1) / threads;
        init_inv_kernel<<<blocks, threads>>>(N);
    }
    {   // inv[index[r]] = r
        int threads = 256;
        int blocks = (M + threads - 1) / threads;
        scatter_inv_kernel<<<blocks, threads>>>(index, M);
    }
    {   // fused copy + Adam update
        int threads = 256;
        long blocks = (n4 + threads - 1) / threads;
        fused_adam_kernel<<<(unsigned)blocks, threads>>>(
            (const float4*)param, grad, (const float4*)exp_avg,
            (const float4*)exp_avg_sq, step_ptr, (float4*)out, n4);
    }
}

// round 3
// speedup vs baseline: 1.2193x; 1.0252x over previous
#include <cuda_runtime.h>
#include <cstdint>

// Sparse Adam: N=1e6 rows, M=250k visible, D=32, out = [3, N, D] f32.
// Inputs (metadata order): param[N*D] f32, grad[M*D] f32, exp_avg[N*D] f32,
// exp_avg_sq[N*D] f32, index[M] i32, step scalar i32.

#define B1 0.9f
#define B2 0.999f
#define EPS 1e-15f
#define LR  1.6e-4f

#define N_MAX 1048576  // >= N = 1,000,000 rows

// Scratch: inverse index map (row -> candidate visible slot). No init pass:
// the fused kernel validates entries with index[r] == row, so stale/zero
// contents are harmless and the output is deterministic.
__device__ int g_inv[N_MAX];

__global__ void scatter_inv_kernel(const int* __restrict__ index, int M) {
    int r = blockIdx.x * blockDim.x + threadIdx.x;
    if (r < M) g_inv[index[r]] = r;
}

// Fused pass: one thread per float4 chunk of the N*D state.
// Reads param/exp_avg/exp_avg_sq (streaming), applies Adam where the row is
// visible (validated inverse map), writes all three output slabs (streaming).
__global__ __launch_bounds__(256) void fused_adam_kernel(
        const float4* __restrict__ param,
        const float*  __restrict__ grad,
        const float4* __restrict__ exp_avg,
        const float4* __restrict__ exp_avg_sq,
        const int*    __restrict__ index,
        const int*    __restrict__ step_ptr,
        float4* __restrict__ out,
        long n4, int M) {
    long gid = (long)blockIdx.x * blockDim.x + threadIdx.x;
    if (gid >= n4) return;

    int row = (int)(gid >> 3);   // 8 float4 chunks per 32-float row
    int c   = (int)(gid & 7);

    // Streaming loads: each byte read exactly once -> evict-first.
    float4 p = __ldcs(param + gid);
    float4 a = __ldcs(exp_avg + gid);
    float4 s = __ldcs(exp_avg_sq + gid);

    int r = g_inv[row];
    bool visible = (r >= 0) && (r < M) && (__ldg(index + r) == row);
    if (visible) {
        int step = step_ptr ? step_ptr[0] : 1000;
        // bc1: 0.9^1000 underflows f32 -> bc1 = 1.0 exactly (matches the
        // float64-exponent reference); bc2 rel-err ~1e-5 << 1e-3 threshold.
        float bc1 = 1.0f - __powf(B1, (float)step);
        float bc2 = 1.0f - __powf(B2, (float)step);
        float inv_sqrt_bc2 = rsqrtf(bc2);
        float lr_c = LR / bc1;

        float4 g = *reinterpret_cast<const float4*>(grad + (long)r * 32 + c * 4);

        a.x = a.x * B1 + (1.0f - B1) * g.x;
        a.y = a.y * B1 + (1.0f - B1) * g.y;
        a.z = a.z * B1 + (1.0f - B1) * g.z;
        a.w = a.w * B1 + (1.0f - B1) * g.w;

        s.x = s.x * B2 + (1.0f - B2) * g.x * g.x;
        s.y = s.y * B2 + (1.0f - B2) * g.y * g.y;
        s.z = s.z * B2 + (1.0f - B2) * g.z * g.z;
        s.w = s.w * B2 + (1.0f - B2) * g.w * g.w;

        p.x -= lr_c * a.x / (sqrtf(s.x) * inv_sqrt_bc2 + EPS);
        p.y -= lr_c * a.y / (sqrtf(s.y) * inv_sqrt_bc2 + EPS);
        p.z -= lr_c * a.z / (sqrtf(s.z) * inv_sqrt_bc2 + EPS);
        p.w -= lr_c * a.w / (sqrtf(s.w) * inv_sqrt_bc2 + EPS);
    }

    __stcs(out + gid, p);
    __stcs(out + n4 + gid, a);
    __stcs(out + 2 * n4 + gid, s);
}

extern "C" void kernel_launch(void* const* d_in, const int* in_sizes, int n_in,
                              void* d_out, int out_size) {
    const float* param      = (const float*)d_in[0];
    const float* grad       = (const float*)d_in[1];
    const float* exp_avg    = (const float*)d_in[2];
    const float* exp_avg_sq = (const float*)d_in[3];
    const int*   index      = (const int*)d_in[4];
    const int*   step_ptr   = (n_in > 5) ? (const int*)d_in[5] : nullptr;

    long ND = (long)in_sizes[0];   // N*D
    int  M  = in_sizes[4];
    long n4 = ND / 4;

    float* out = (float*)d_out;

    {   // inv[index[r]] = r  (validated in the fused pass; no init needed)
        int threads = 256;
        int blocks = (M + threads - 1) / threads;
        scatter_inv_kernel<<<blocks, threads>>>(index, M);
    }
    {   // fused copy + Adam update
        int threads = 256;
        long blocks = (n4 + threads - 1) / threads;
        fused_adam_kernel<<<(unsigned)blocks, threads>>>(
            (const float4*)param, grad, (const float4*)exp_avg,
            (const float4*)exp_avg_sq, index, step_ptr, (float4*)out, n4, M);
    }
}